// round 15
// baseline (speedup 1.0000x reference)
#include <cuda_runtime.h>
#include <cuda_fp16.h>
#include <math.h>
#include <stdint.h>

// Problem dims (fixed)
#define BATCH 32
#define SEQ   512
#define N_TOK (BATCH * SEQ)   // 16384
#define DIM   256
#define HID   512
#define PFF   2048
#define NHD   8
#define HDD   64
#define NMAXN 15
#define QKV_STR 1536

// ---------------- scratch (device globals: allocation-free) ----------------
__device__ float  g_x[N_TOK * DIM];
__device__ float  g_tmp[N_TOK * DIM];
__device__ float  g_h32[N_TOK * HID];
__device__ float  g_bqkv[2 * QKV_STR];
__device__ __half g_x16[N_TOK * DIM];
__device__ __half g_agg16[N_TOK * DIM];
__device__ __half g_h16[N_TOK * HID];
__device__ __half g_qkv16[N_TOK * QKV_STR];
__device__ __half g_o16[N_TOK * HID];
__device__ __half g_ff16[N_TOK * PFF];
#define WT_SOC   0
#define WT_PROJ  65536
#define WT_LAYER 196608
#define WT_PER_L 3145728
#define L_QKV 0
#define L_WO  786432
#define L_W1  1048576
#define L_W2  2097152
__device__ __half g_wt16[WT_LAYER + 2 * WT_PER_L];

// ======================= helpers =======================
__device__ __forceinline__ uint32_t smem_u32(const void* p) {
    uint32_t a;
    asm("{ .reg .u64 t; cvta.to.shared.u64 t, %1; cvt.u32.u64 %0, t; }" : "=r"(a) : "l"(p));
    return a;
}
__device__ __forceinline__ void cp16(uint32_t dst, const void* src) {
    asm volatile("cp.async.cg.shared.global [%0], [%1], 16;" :: "r"(dst), "l"(src));
}
#define CP_COMMIT() asm volatile("cp.async.commit_group;" ::: "memory")
#define CP_WAIT(n)  asm volatile("cp.async.wait_group %0;" :: "n"(n) : "memory")

__device__ __forceinline__ void mma_f16(float* c, const uint32_t* a, const uint32_t* b) {
    asm volatile(
        "mma.sync.aligned.m16n8k16.row.col.f32.f16.f16.f32 "
        "{%0,%1,%2,%3}, {%4,%5,%6,%7}, {%8,%9}, {%0,%1,%2,%3};\n"
        : "+f"(c[0]), "+f"(c[1]), "+f"(c[2]), "+f"(c[3])
        : "r"(a[0]), "r"(a[1]), "r"(a[2]), "r"(a[3]), "r"(b[0]), "r"(b[1]));
}
__device__ __forceinline__ void ldsm_x2_t(uint32_t& r0, uint32_t& r1, uint32_t addr) {
    asm volatile("ldmatrix.sync.aligned.m8n8.x2.trans.shared.b16 {%0,%1}, [%2];"
                 : "=r"(r0), "=r"(r1) : "r"(addr));
}
__device__ __forceinline__ uint32_t pack2h(float a, float b) {
    __half2 h = __floats2half2_rn(a, b);
    return *(uint32_t*)&h;
}
__device__ __forceinline__ float warpSum(float v) {
#pragma unroll
    for (int o = 16; o; o >>= 1) v += __shfl_xor_sync(0xffffffffu, v, o);
    return v;
}

// ============== fp16 tensor-core GEMM (Round-8 proven config) ==============
#define GSTAGE_B 20480
#define GEMM_SMEM (2 * GSTAGE_B)

template <bool RELU, bool RES, int OUT>
__global__ void __launch_bounds__(128) tc_gemm(const __half* __restrict__ A,
                                               const __half* __restrict__ Bt,
                                               const float* __restrict__ bias,
                                               const float* __restrict__ Cin,
                                               float* __restrict__ C32,
                                               __half* __restrict__ C16,
                                               int M, int N, int K) {
    extern __shared__ char smc[];
    int tid = threadIdx.x;
    int m0 = blockIdx.y * 128, n0 = blockIdx.x * 128;
    int lane = tid & 31, wid = tid >> 5;
    int wm = wid & 1, wn = wid >> 1;
    int g = lane >> 2, tig = lane & 3;
    uint32_t sb = smem_u32(smc);

    float acc[4][8][4];
#pragma unroll
    for (int mt = 0; mt < 4; mt++)
#pragma unroll
        for (int nt = 0; nt < 8; nt++)
#pragma unroll
            for (int r = 0; r < 4; r++) acc[mt][nt][r] = 0.f;

    int nk = K >> 5;

    auto issue = [&](int s, int i) {
#pragma unroll
        for (int p = 0; p < 4; p++) {
            int idx = p * 128 + tid;
            int row = idx >> 2, c = idx & 3;
            uint32_t da = sb + (uint32_t)(s * GSTAGE_B + row * 80 + c * 16);
            uint32_t db = da + 10240;
            cp16(da, A + (size_t)(m0 + row) * K + i * 32 + c * 8);
            cp16(db, Bt + (size_t)(n0 + row) * K + i * 32 + c * 8);
        }
        CP_COMMIT();
    };

    issue(0, 0);
    for (int i = 0; i < nk; i++) {
        int s = i & 1;
        CP_WAIT(0);
        __syncthreads();
        if (i + 1 < nk) issue(s ^ 1, i + 1);
        const uint32_t* As = (const uint32_t*)(smc + s * GSTAGE_B);
        const uint32_t* Bs = As + 2560;
#pragma unroll
        for (int ks = 0; ks < 2; ks++) {
            uint32_t af[4][4], bf[8][2];
#pragma unroll
            for (int mt = 0; mt < 4; mt++) {
                int m = wm * 64 + mt * 16 + g;
                af[mt][0] = As[m * 20 + ks * 8 + tig];
                af[mt][1] = As[(m + 8) * 20 + ks * 8 + tig];
                af[mt][2] = As[m * 20 + ks * 8 + tig + 4];
                af[mt][3] = As[(m + 8) * 20 + ks * 8 + tig + 4];
            }
#pragma unroll
            for (int nt = 0; nt < 8; nt++) {
                int n = wn * 64 + nt * 8 + g;
                bf[nt][0] = Bs[n * 20 + ks * 8 + tig];
                bf[nt][1] = Bs[n * 20 + ks * 8 + tig + 4];
            }
#pragma unroll
            for (int mt = 0; mt < 4; mt++)
#pragma unroll
                for (int nt = 0; nt < 8; nt++)
                    mma_f16(acc[mt][nt], af[mt], bf[nt]);
        }
    }

#pragma unroll
    for (int mt = 0; mt < 4; mt++) {
#pragma unroll
        for (int nt = 0; nt < 8; nt++) {
            int row0 = m0 + wm * 64 + mt * 16 + g;
            int col = n0 + wn * 64 + nt * 8 + tig * 2;
            float b0 = __ldg(&bias[col]), b1 = __ldg(&bias[col + 1]);
            float v0 = acc[mt][nt][0] + b0, v1 = acc[mt][nt][1] + b1;
            float v2 = acc[mt][nt][2] + b0, v3 = acc[mt][nt][3] + b1;
            if (RES) {
                float2 q0 = *(const float2*)(Cin + (size_t)row0 * N + col);
                float2 q1 = *(const float2*)(Cin + (size_t)(row0 + 8) * N + col);
                v0 += q0.x; v1 += q0.y; v2 += q1.x; v3 += q1.y;
            }
            if (RELU) {
                v0 = fmaxf(v0, 0.f); v1 = fmaxf(v1, 0.f);
                v2 = fmaxf(v2, 0.f); v3 = fmaxf(v3, 0.f);
            }
            if (OUT == 3 && col < HID) {
                v0 *= 0.125f; v1 *= 0.125f; v2 *= 0.125f; v3 *= 0.125f;
            }
            if (OUT == 0 || OUT == 2) {
                *(float2*)(C32 + (size_t)row0 * N + col) = make_float2(v0, v1);
                *(float2*)(C32 + (size_t)(row0 + 8) * N + col) = make_float2(v2, v3);
            }
            if (OUT >= 1) {
                *(uint32_t*)(C16 + (size_t)row0 * N + col) = pack2h(v0, v1);
                *(uint32_t*)(C16 + (size_t)(row0 + 8) * N + col) = pack2h(v2, v3);
            }
        }
    }
}

// ============== fused GEMM + residual + LayerNorm (N=512 full row) ==============
// C_ln = LN(Cin + A@Bt^T + bias) * g + b.  Tile 64 x 512, 256 threads = 8 warps,
// warp wn = wid covers cols wid*64..+63, all warps share the 64 rows.
// Writes out32 (always) and out16 (if non-null).
#define LSTAGE_A 5120
#define LSTAGE_B2 40960
#define LSTAGE (LSTAGE_A + LSTAGE_B2)           // 46080
#define LRED_OFF (2 * LSTAGE)                   // 92160
#define GEMM_LN_SMEM (LRED_OFF + 64 * 8 * 2 * 4)  // +4096

__global__ void __launch_bounds__(256) tc_gemm_ln(const __half* __restrict__ A,
                                                  const __half* __restrict__ Bt,
                                                  const float* __restrict__ bias,
                                                  const float* __restrict__ Cin,
                                                  const float* __restrict__ lng,
                                                  const float* __restrict__ lnb,
                                                  float* __restrict__ out32,
                                                  __half* __restrict__ out16,
                                                  int K) {
    extern __shared__ char smc[];
    float* red = (float*)(smc + LRED_OFF);      // [64][8] sum, then [64][8] sumsq
    int tid = threadIdx.x;
    int m0 = blockIdx.x * 64;
    int lane = tid & 31, wid = tid >> 5;
    int g = lane >> 2, tig = lane & 3;
    uint32_t sb = smem_u32(smc);

    float acc[4][8][4];
#pragma unroll
    for (int mt = 0; mt < 4; mt++)
#pragma unroll
        for (int nt = 0; nt < 8; nt++)
#pragma unroll
            for (int r = 0; r < 4; r++) acc[mt][nt][r] = 0.f;

    int nk = K >> 5;

    auto issue = [&](int s, int i) {
        // A: 64 rows x 32 halves = 256 chunks (1/thread)
        {
            int row = tid >> 2, c = tid & 3;
            cp16(sb + (uint32_t)(s * LSTAGE + row * 80 + c * 16),
                 A + (size_t)(m0 + row) * K + i * 32 + c * 8);
        }
        // B: 512 rows x 32 halves = 2048 chunks (8/thread)
#pragma unroll
        for (int p = 0; p < 8; p++) {
            int idx = p * 256 + tid;
            int row = idx >> 2, c = idx & 3;
            cp16(sb + (uint32_t)(s * LSTAGE + LSTAGE_A + row * 80 + c * 16),
                 Bt + (size_t)row * K + i * 32 + c * 8);
        }
        CP_COMMIT();
    };

    issue(0, 0);
    for (int i = 0; i < nk; i++) {
        int s = i & 1;
        CP_WAIT(0);
        __syncthreads();
        if (i + 1 < nk) issue(s ^ 1, i + 1);
        const uint32_t* As = (const uint32_t*)(smc + s * LSTAGE);
        const uint32_t* Bs = (const uint32_t*)(smc + s * LSTAGE + LSTAGE_A);
#pragma unroll
        for (int ks = 0; ks < 2; ks++) {
            uint32_t af[4][4], bf[8][2];
#pragma unroll
            for (int mt = 0; mt < 4; mt++) {
                int m = mt * 16 + g;
                af[mt][0] = As[m * 20 + ks * 8 + tig];
                af[mt][1] = As[(m + 8) * 20 + ks * 8 + tig];
                af[mt][2] = As[m * 20 + ks * 8 + tig + 4];
                af[mt][3] = As[(m + 8) * 20 + ks * 8 + tig + 4];
            }
#pragma unroll
            for (int nt = 0; nt < 8; nt++) {
                int n = wid * 64 + nt * 8 + g;
                bf[nt][0] = Bs[n * 20 + ks * 8 + tig];
                bf[nt][1] = Bs[n * 20 + ks * 8 + tig + 4];
            }
#pragma unroll
            for (int mt = 0; mt < 4; mt++)
#pragma unroll
                for (int nt = 0; nt < 8; nt++)
                    mma_f16(acc[mt][nt], af[mt], bf[nt]);
        }
    }
    __syncthreads();   // done with smem stages; reuse for reduction

    // v = acc + bias + residual; accumulate per-row partial sums
    float vv[4][8][4];
    float rs[8], rq[8];
#pragma unroll
    for (int r = 0; r < 8; r++) { rs[r] = 0.f; rq[r] = 0.f; }
#pragma unroll
    for (int mt = 0; mt < 4; mt++) {
#pragma unroll
        for (int nt = 0; nt < 8; nt++) {
            int row0 = m0 + mt * 16 + g;
            int col = wid * 64 + nt * 8 + tig * 2;
            float b0 = __ldg(&bias[col]), b1 = __ldg(&bias[col + 1]);
            float2 q0 = *(const float2*)(Cin + (size_t)row0 * HID + col);
            float2 q1 = *(const float2*)(Cin + (size_t)(row0 + 8) * HID + col);
            float v0 = acc[mt][nt][0] + b0 + q0.x;
            float v1 = acc[mt][nt][1] + b1 + q0.y;
            float v2 = acc[mt][nt][2] + b0 + q1.x;
            float v3 = acc[mt][nt][3] + b1 + q1.y;
            vv[mt][nt][0] = v0; vv[mt][nt][1] = v1;
            vv[mt][nt][2] = v2; vv[mt][nt][3] = v3;
            rs[mt * 2] += v0 + v1;       rq[mt * 2] += v0 * v0 + v1 * v1;
            rs[mt * 2 + 1] += v2 + v3;   rq[mt * 2 + 1] += v2 * v2 + v3 * v3;
        }
    }
    // reduce across the 4 tig-lanes sharing each row
#pragma unroll
    for (int r = 0; r < 8; r++) {
        rs[r] += __shfl_xor_sync(0xffffffffu, rs[r], 1);
        rs[r] += __shfl_xor_sync(0xffffffffu, rs[r], 2);
        rq[r] += __shfl_xor_sync(0xffffffffu, rq[r], 1);
        rq[r] += __shfl_xor_sync(0xffffffffu, rq[r], 2);
    }
    if (tig == 0) {
#pragma unroll
        for (int r = 0; r < 8; r++) {
            int row = (r >> 1) * 16 + (r & 1) * 8 + g;   // r = mt*2 + half
            red[row * 8 + wid] = rs[r];
            red[512 + row * 8 + wid] = rq[r];
        }
    }
    __syncthreads();

    // finalize LN per row and store
#pragma unroll
    for (int mt = 0; mt < 4; mt++) {
#pragma unroll
        for (int half = 0; half < 2; half++) {
            int row = mt * 16 + half * 8 + g;
            float su = 0.f, sq = 0.f;
#pragma unroll
            for (int wdx = 0; wdx < 8; wdx++) {
                su += red[row * 8 + wdx];
                sq += red[512 + row * 8 + wdx];
            }
            float mu = su * (1.f / HID);
            float var = sq * (1.f / HID) - mu * mu;
            float inv = rsqrtf(fmaxf(var, 0.f) + 1e-5f);
            int grow = m0 + row;
#pragma unroll
            for (int nt = 0; nt < 8; nt++) {
                int col = wid * 64 + nt * 8 + tig * 2;
                float g0 = __ldg(&lng[col]), g1 = __ldg(&lng[col + 1]);
                float c0 = __ldg(&lnb[col]), c1 = __ldg(&lnb[col + 1]);
                float va = vv[mt][nt][half * 2 + 0];
                float vb2 = vv[mt][nt][half * 2 + 1];
                float o0 = (va - mu) * inv * g0 + c0;
                float o1 = (vb2 - mu) * inv * g1 + c1;
                *(float2*)(out32 + (size_t)grow * HID + col) = make_float2(o0, o1);
                if (out16)
                    *(uint32_t*)(out16 + (size_t)grow * HID + col) = pack2h(o0, o1);
            }
        }
    }
}

// ============== fp16 flash attention (Round-8 proven: BQ=128, BK=64, dbl-buf KV) =======
#define HOQ  0
#define HOK0 9216
#define HKSZ 4608
#define HOV0 18432
#define HVSZ 4608
#define HOP  27648
#define FOM  18432
#define ATTN_SMEM (73728 + 512)

__global__ void __launch_bounds__(256) attn_mma(const __half* __restrict__ qkv,
                                                const int* __restrict__ src,
                                                __half* __restrict__ O) {
    extern __shared__ char sac[];
    float* saf = (float*)sac;
    const uint32_t* smw = (const uint32_t*)sac;
    uint32_t sb = smem_u32(sac);
    int bh = blockIdx.y;
    int b = bh >> 3, h = bh & 7;
    int q0 = blockIdx.x * 128;
    int tid = threadIdx.x;
    int lane = tid & 31, w = tid >> 5;
    int g = lane >> 2, tig = lane & 3;

    const __half* Qg = qkv + (size_t)(b * SEQ + q0) * QKV_STR + h * HDD;
#pragma unroll
    for (int p = 0; p < 4; p++) {
        int idx = p * 256 + tid;
        int row = idx >> 3, c = idx & 7;
        cp16(sb + (uint32_t)(row * 144 + c * 16), Qg + (size_t)row * QKV_STR + c * 8);
    }
    CP_COMMIT();

    auto load_kv = [&](int s, int kt) {
        const __half* Kg = qkv + (size_t)(b * SEQ + kt * 64) * QKV_STR + HID + h * HDD;
        const __half* Vg = Kg + HID;
#pragma unroll
        for (int p = 0; p < 2; p++) {
            int idx = p * 256 + tid;
            int row = idx >> 3, c = idx & 7;
            cp16(sb + (uint32_t)((HOK0 + s * HKSZ + row * 72) * 2 + c * 16),
                 Kg + (size_t)row * QKV_STR + c * 8);
            cp16(sb + (uint32_t)((HOV0 + s * HVSZ + row * 72) * 2 + c * 16),
                 Vg + (size_t)row * QKV_STR + c * 8);
        }
        CP_COMMIT();
        if (tid < 64)
            saf[FOM + s * 64 + tid] = (src[b * SEQ + kt * 64 + tid] != 0) ? 0.f : -1e10f;
    };

    load_kv(0, 0);

    float o_acc[8][4];
#pragma unroll
    for (int nt = 0; nt < 8; nt++)
#pragma unroll
        for (int r = 0; r < 4; r++) o_acc[nt][r] = 0.f;
    float mr0 = -1e30f, mr1 = -1e30f, lr0 = 0.f, lr1 = 0.f;

    for (int kt = 0; kt < SEQ / 64; kt++) {
        int s = kt & 1;
        CP_WAIT(0);
        __syncthreads();
        if (kt + 1 < SEQ / 64) load_kv(s ^ 1, kt + 1);
        int kbw = (HOK0 + s * HKSZ) >> 1;
        uint32_t vbb = sb + (uint32_t)((HOV0 + s * HVSZ) * 2);
        const float* msk = saf + FOM + s * 64;

        float sc[8][4];
#pragma unroll
        for (int nt = 0; nt < 8; nt++)
#pragma unroll
            for (int r = 0; r < 4; r++) sc[nt][r] = 0.f;
#pragma unroll
        for (int kk = 0; kk < 4; kk++) {
            uint32_t a[4];
            int r0 = (w * 16 + g) * 36 + kk * 8 + tig;
            int r1 = (w * 16 + 8 + g) * 36 + kk * 8 + tig;
            a[0] = smw[r0]; a[1] = smw[r1];
            a[2] = smw[r0 + 4]; a[3] = smw[r1 + 4];
#pragma unroll
            for (int nt = 0; nt < 8; nt++) {
                uint32_t bb[2];
                int rb = kbw + (nt * 8 + g) * 36 + kk * 8 + tig;
                bb[0] = smw[rb]; bb[1] = smw[rb + 4];
                mma_f16(sc[nt], a, bb);
            }
        }

        float m0 = -1e30f, m1 = -1e30f;
#pragma unroll
        for (int nt = 0; nt < 8; nt++) {
            float k0 = msk[nt * 8 + tig * 2];
            float k1 = msk[nt * 8 + tig * 2 + 1];
            sc[nt][0] += k0; sc[nt][1] += k1;
            sc[nt][2] += k0; sc[nt][3] += k1;
            m0 = fmaxf(m0, fmaxf(sc[nt][0], sc[nt][1]));
            m1 = fmaxf(m1, fmaxf(sc[nt][2], sc[nt][3]));
        }
        m0 = fmaxf(m0, __shfl_xor_sync(0xffffffffu, m0, 1));
        m0 = fmaxf(m0, __shfl_xor_sync(0xffffffffu, m0, 2));
        m1 = fmaxf(m1, __shfl_xor_sync(0xffffffffu, m1, 1));
        m1 = fmaxf(m1, __shfl_xor_sync(0xffffffffu, m1, 2));
        float mn0 = fmaxf(mr0, m0), mn1 = fmaxf(mr1, m1);
        float s0 = __expf(mr0 - mn0), s1 = __expf(mr1 - mn1);
        mr0 = mn0; mr1 = mn1;
        float l0 = 0.f, l1 = 0.f;
        uint32_t* smwp = (uint32_t*)sac;
        int pw0 = (HOP >> 1) + (w * 16 + g) * 36 + tig;
        int pw1 = (HOP >> 1) + (w * 16 + 8 + g) * 36 + tig;
#pragma unroll
        for (int nt = 0; nt < 8; nt++) {
            float p0 = __expf(sc[nt][0] - mn0);
            float p1 = __expf(sc[nt][1] - mn0);
            float p2 = __expf(sc[nt][2] - mn1);
            float p3 = __expf(sc[nt][3] - mn1);
            l0 += p0 + p1; l1 += p2 + p3;
            smwp[pw0 + nt * 4] = pack2h(p0, p1);
            smwp[pw1 + nt * 4] = pack2h(p2, p3);
        }
        l0 += __shfl_xor_sync(0xffffffffu, l0, 1);
        l0 += __shfl_xor_sync(0xffffffffu, l0, 2);
        l1 += __shfl_xor_sync(0xffffffffu, l1, 1);
        l1 += __shfl_xor_sync(0xffffffffu, l1, 2);
        lr0 = lr0 * s0 + l0;
        lr1 = lr1 * s1 + l1;
#pragma unroll
        for (int nt = 0; nt < 8; nt++) {
            o_acc[nt][0] *= s0; o_acc[nt][1] *= s0;
            o_acc[nt][2] *= s1; o_acc[nt][3] *= s1;
        }
        __syncwarp();

        int j = lane & 15;
#pragma unroll
        for (int kk = 0; kk < 4; kk++) {
            uint32_t a[4];
            int r0 = (HOP >> 1) + (w * 16 + g) * 36 + kk * 8 + tig;
            int r1 = (HOP >> 1) + (w * 16 + 8 + g) * 36 + kk * 8 + tig;
            a[0] = smwp[r0]; a[1] = smwp[r1];
            a[2] = smwp[r0 + 4]; a[3] = smwp[r1 + 4];
            uint32_t vrow = vbb + (uint32_t)((kk * 16 + j) * 144);
#pragma unroll
            for (int nt = 0; nt < 8; nt++) {
                uint32_t bb0, bb1;
                ldsm_x2_t(bb0, bb1, vrow + nt * 16);
                uint32_t bb[2] = {bb0, bb1};
                mma_f16(o_acc[nt], a, bb);
            }
        }
    }

    float i0 = 1.f / lr0, i1 = 1.f / lr1;
    int row0 = b * SEQ + q0 + w * 16 + g;
    __half* Ob = O + (size_t)row0 * HID + h * HDD;
#pragma unroll
    for (int nt = 0; nt < 8; nt++) {
        *(uint32_t*)(Ob + nt * 8 + tig * 2) = pack2h(o_acc[nt][0] * i0, o_acc[nt][1] * i0);
        *(uint32_t*)(Ob + 8 * HID + nt * 8 + tig * 2) = pack2h(o_acc[nt][2] * i1, o_acc[nt][3] * i1);
    }
}

// ---------------- fused weight transposes (fp32 -> fp16 Bt[n][k]) ----------------
#define NJOBS 14
struct TParams {
    const float* in[NJOBS];
    __half* out[NJOBS];
    int R[NJOBS], C[NJOBS], tstart[NJOBS];
};
__global__ void transpose_all(TParams p) {
    __shared__ float t[32][33];
    int tile = blockIdx.x;
    int j = 0;
#pragma unroll
    for (int q = 1; q < NJOBS; q++)
        if (tile >= p.tstart[q]) j = q;
    int local = tile - p.tstart[j];
    int R = p.R[j], Cc = p.C[j];
    int tilesX = Cc >> 5;
    int c0 = (local % tilesX) * 32, r0 = (local / tilesX) * 32;
    const float* in = p.in[j];
    __half* out = p.out[j];
    int x = threadIdx.x, y = threadIdx.y;
#pragma unroll
    for (int i = 0; i < 32; i += 8) t[y + i][x] = in[(size_t)(r0 + y + i) * Cc + c0 + x];
    __syncthreads();
#pragma unroll
    for (int i = 0; i < 32; i += 8)
        out[(size_t)(c0 + y + i) * R + r0 + x] = __float2half_rn(t[x][y + i]);
}

// ---------------- bias concat (both layers, one launch) ----------------
__global__ void concat_bias(const float* __restrict__ bq, const float* __restrict__ bk,
                            const float* __restrict__ bv, float* __restrict__ out) {
    int i = blockIdx.x * 256 + threadIdx.x;
    int l = i / QKV_STR, r = i % QKV_STR;
    float v;
    if (r < HID) v = bq[l * HID + r];
    else if (r < 2 * HID) v = bk[l * HID + r - HID];
    else v = bv[l * HID + r - 2 * HID];
    out[i] = v;
}

// ---------------- embed + PE + time (MUFU fast math, fp32 out) ----------------
__global__ void embed_kernel(const int* __restrict__ src,
                             const float* __restrict__ tint,
                             const float* __restrict__ emb,
                             const float* __restrict__ timeW,
                             const float* __restrict__ timeb,
                             float* __restrict__ x) {
    int n = blockIdx.x;
    int d = threadIdx.x;
    int s = n & (SEQ - 1);
    int v = src[n];
    float e = emb[(size_t)v * DIM + d];
    int i2 = (d >> 1) * 2;
    float div = __expf((float)i2 * (-9.210340371976184f / (float)DIM));
    float ang = (float)s * div;
    float sn, cs;
    __sincosf(ang, &sn, &cs);
    float pe = (d & 1) ? cs : sn;
    float tv = tint[n];
    x[n * DIM + d] = e + pe + tv * timeW[d] + timeb[d];
}

// ---------------- neighbor mean aggregation (warp-per-token, float4) --------
__global__ void __launch_bounds__(256) agg_kernel(const int* __restrict__ nidx,
                           const int* __restrict__ ncnt,
                           const float* __restrict__ x,
                           __half* __restrict__ agg) {
    int w = threadIdx.x >> 5, lane = threadIdx.x & 31;
    int n = blockIdx.x * 8 + w;
    int cnt = ncnt[n];
    float4 s0 = make_float4(0.f, 0.f, 0.f, 0.f);
    float4 s1 = s0;
    const int* nb = nidx + n * NMAXN;
    for (int j = 0; j < cnt; j++) {
        int idx = __ldg(&nb[j]);
        const float4* xr = (const float4*)(x + (size_t)idx * DIM);
        float4 a = xr[lane], b = xr[lane + 32];
        s0.x += a.x; s0.y += a.y; s0.z += a.z; s0.w += a.w;
        s1.x += b.x; s1.y += b.y; s1.z += b.z; s1.w += b.w;
    }
    float iv = 1.f / (float)(cnt > 1 ? cnt : 1);
    uint2* ow = (uint2*)(agg + (size_t)n * DIM);
    ow[lane] = make_uint2(pack2h(s0.x * iv, s0.y * iv), pack2h(s0.z * iv, s0.w * iv));
    ow[lane + 32] = make_uint2(pack2h(s1.x * iv, s1.y * iv), pack2h(s1.z * iv, s1.w * iv));
}

// ---------------- soc LN (warp-per-row): writes out_x fp32 + x16 fp16 ----------------
__global__ void __launch_bounds__(256) soc_ln_kernel(const float* __restrict__ tmp,
                              const float* __restrict__ g,
                              const float* __restrict__ beta,
                              const int* __restrict__ ncnt,
                              const int* __restrict__ src,
                              const float* __restrict__ x,
                              __half* __restrict__ x16,
                              float* __restrict__ out_x) {
    int w = threadIdx.x >> 5, lane = threadIdx.x & 31;
    int n = blockIdx.x * 8 + w;
    const float4* r = (const float4*)(tmp + (size_t)n * DIM);
    float4 v[2];
    float s = 0.f;
#pragma unroll
    for (int j = 0; j < 2; j++) {
        v[j] = r[lane + 32 * j];
        s += v[j].x + v[j].y + v[j].z + v[j].w;
    }
    float mu = warpSum(s) * (1.f / DIM);
    float q = 0.f;
#pragma unroll
    for (int j = 0; j < 2; j++) {
        float a = v[j].x - mu, b2 = v[j].y - mu, c = v[j].z - mu, d2 = v[j].w - mu;
        q += a * a + b2 * b2 + c * c + d2 * d2;
    }
    float inv = rsqrtf(warpSum(q) * (1.f / DIM) + 1e-5f);
    int cnt = ncnt[n];
    int pad = (src[n] == 0);
    const float4* gg = (const float4*)g;
    const float4* bb = (const float4*)beta;
    const float4* xr = (const float4*)(x + (size_t)n * DIM);
    float4* ow = (float4*)(out_x + (size_t)n * DIM);
    uint32_t* xw = (uint32_t*)(x16 + (size_t)n * DIM);
#pragma unroll
    for (int j = 0; j < 2; j++) {
        float4 gv = gg[lane + 32 * j], bv = bb[lane + 32 * j];
        float4 xv = xr[lane + 32 * j];
        float y0 = fmaxf((v[j].x - mu) * inv * gv.x + bv.x, 0.f);
        float y1 = fmaxf((v[j].y - mu) * inv * gv.y + bv.y, 0.f);
        float y2 = fmaxf((v[j].z - mu) * inv * gv.z + bv.z, 0.f);
        float y3 = fmaxf((v[j].w - mu) * inv * gv.w + bv.w, 0.f);
        float s0 = (cnt > 0) ? y0 : xv.x; if (pad) s0 = 0.f;
        float s1 = (cnt > 0) ? y1 : xv.y; if (pad) s1 = 0.f;
        float s2 = (cnt > 0) ? y2 : xv.z; if (pad) s2 = 0.f;
        float s3 = (cnt > 0) ? y3 : xv.w; if (pad) s3 = 0.f;
        float o0 = xv.x + 0.2f * s0, o1 = xv.y + 0.2f * s1;
        float o2 = xv.z + 0.2f * s2, o3 = xv.w + 0.2f * s3;
        ow[lane + 32 * j] = make_float4(o0, o1, o2, o3);
        xw[(lane + 32 * j) * 2] = pack2h(o0, o1);
        xw[(lane + 32 * j) * 2 + 1] = pack2h(o2, o3);
    }
}

// ---------------- host side ----------------
template <bool RELU, bool RES, int OUT>
static void launch_gemm(const __half* A, const __half* Bt, const float* bias,
                        const float* Cin, float* C32, __half* C16, int M, int Nn, int K) {
    dim3 grid(Nn / 128, M / 128);
    tc_gemm<RELU, RES, OUT><<<grid, 128, GEMM_SMEM>>>(A, Bt, bias, Cin, C32, C16, M, Nn, K);
}

extern "C" void kernel_launch(void* const* d_in, const int* in_sizes, int n_in,
                              void* d_out, int out_size) {
    const int*   src   = (const int*)d_in[0];
    const int*   nidx  = (const int*)d_in[2];
    const int*   ncnt  = (const int*)d_in[3];
    const float* tint  = (const float*)d_in[4];
    const float* emb   = (const float*)d_in[5];
    const float* timeW = (const float*)d_in[6];
    const float* timeb = (const float*)d_in[7];
    const float* socW  = (const float*)d_in[8];
    const float* socb  = (const float*)d_in[9];
    const float* socg  = (const float*)d_in[10];
    const float* socbe = (const float*)d_in[11];
    const float* projW = (const float*)d_in[12];
    const float* projb = (const float*)d_in[13];
    const float* Wq    = (const float*)d_in[14];
    const float* bq    = (const float*)d_in[15];
    const float* Wk    = (const float*)d_in[16];
    const float* bk    = (const float*)d_in[17];
    const float* Wv    = (const float*)d_in[18];
    const float* bv    = (const float*)d_in[19];
    const float* Wo    = (const float*)d_in[20];
    const float* bo    = (const float*)d_in[21];
    const float* ln1g  = (const float*)d_in[22];
    const float* ln1b  = (const float*)d_in[23];
    const float* W1    = (const float*)d_in[24];
    const float* b1    = (const float*)d_in[25];
    const float* W2    = (const float*)d_in[26];
    const float* b2    = (const float*)d_in[27];
    const float* ln2g  = (const float*)d_in[28];
    const float* ln2b  = (const float*)d_in[29];

    float *x, *tmp, *h32, *bqkv;
    __half *x16, *agg16, *h16, *qkv16, *o16, *ff16, *wt16;
    void* p;
    cudaGetSymbolAddress(&p, g_x);     x     = (float*)p;
    cudaGetSymbolAddress(&p, g_tmp);   tmp   = (float*)p;
    cudaGetSymbolAddress(&p, g_h32);   h32   = (float*)p;
    cudaGetSymbolAddress(&p, g_bqkv);  bqkv  = (float*)p;
    cudaGetSymbolAddress(&p, g_x16);   x16   = (__half*)p;
    cudaGetSymbolAddress(&p, g_agg16); agg16 = (__half*)p;
    cudaGetSymbolAddress(&p, g_h16);   h16   = (__half*)p;
    cudaGetSymbolAddress(&p, g_qkv16); qkv16 = (__half*)p;
    cudaGetSymbolAddress(&p, g_o16);   o16   = (__half*)p;
    cudaGetSymbolAddress(&p, g_ff16);  ff16  = (__half*)p;
    cudaGetSymbolAddress(&p, g_wt16);  wt16  = (__half*)p;

    cudaFuncSetAttribute(tc_gemm<false, true, 0>,  cudaFuncAttributeMaxDynamicSharedMemorySize, GEMM_SMEM);
    cudaFuncSetAttribute(tc_gemm<false, false, 2>, cudaFuncAttributeMaxDynamicSharedMemorySize, GEMM_SMEM);
    cudaFuncSetAttribute(tc_gemm<false, false, 3>, cudaFuncAttributeMaxDynamicSharedMemorySize, GEMM_SMEM);
    cudaFuncSetAttribute(tc_gemm<true, false, 1>,  cudaFuncAttributeMaxDynamicSharedMemorySize, GEMM_SMEM);
    cudaFuncSetAttribute(tc_gemm_ln, cudaFuncAttributeMaxDynamicSharedMemorySize, GEMM_LN_SMEM);
    cudaFuncSetAttribute(attn_mma, cudaFuncAttributeMaxDynamicSharedMemorySize, ATTN_SMEM);

    float* out_h = (float*)d_out;
    float* out_x = (float*)d_out + N_TOK * HID;

    // --- fused weight transposes (single launch, fp32 -> fp16) ---
    __half* socT  = wt16 + WT_SOC;
    __half* projT = wt16 + WT_PROJ;
    {
        TParams tp;
        int idx = 0, cum = 0;
        auto add = [&](const float* in, __half* out, int R, int C) {
            tp.in[idx] = in; tp.out[idx] = out; tp.R[idx] = R; tp.C[idx] = C;
            tp.tstart[idx] = cum;
            cum += (R / 32) * (C / 32);
            idx++;
        };
        add(socW, socT, DIM, DIM);
        add(projW, projT, DIM, HID);
        for (int l = 0; l < 2; l++) {
            __half* base = wt16 + WT_LAYER + (size_t)l * WT_PER_L;
            add(Wq + (size_t)l * HID * HID, base + L_QKV + 0 * 262144, HID, HID);
            add(Wk + (size_t)l * HID * HID, base + L_QKV + 1 * 262144, HID, HID);
            add(Wv + (size_t)l * HID * HID, base + L_QKV + 2 * 262144, HID, HID);
            add(Wo + (size_t)l * HID * HID, base + L_WO, HID, HID);
            add(W1 + (size_t)l * HID * PFF, base + L_W1, HID, PFF);
            add(W2 + (size_t)l * PFF * HID, base + L_W2, PFF, HID);
        }
        transpose_all<<<cum, dim3(32, 8)>>>(tp);
    }
    concat_bias<<<12, 256>>>(bq, bk, bv, bqkv);

    // front end
    embed_kernel<<<N_TOK, 256>>>(src, tint, emb, timeW, timeb, x);
    agg_kernel<<<N_TOK / 8, 256>>>(nidx, ncnt, x, agg16);
    launch_gemm<false, true, 0>(agg16, socT, socb, x, tmp, (__half*)0, N_TOK, DIM, DIM);
    soc_ln_kernel<<<N_TOK / 8, 256>>>(tmp, socg, socbe, ncnt, src, x, x16, out_x);
    launch_gemm<false, false, 2>(x16, projT, projb, (const float*)0, h32, h16, N_TOK, HID, DIM);

    for (int l = 0; l < 2; l++) {
        __half* base = wt16 + WT_LAYER + (size_t)l * WT_PER_L;
        launch_gemm<false, false, 3>(h16, base + L_QKV, bqkv + l * QKV_STR, (const float*)0,
                                     (float*)0, qkv16, N_TOK, QKV_STR, HID);
        attn_mma<<<dim3(SEQ / 128, BATCH * NHD), 256, ATTN_SMEM>>>(qkv16, src, o16);
        // fused: h = LN1(h + o @ Wo + bo)  (writes h32 + h16)
        tc_gemm_ln<<<N_TOK / 64, 256, GEMM_LN_SMEM>>>(
            o16, base + L_WO, bo + l * HID, h32,
            ln1g + l * HID, ln1b + l * HID, h32, h16, HID);
        launch_gemm<true, false, 1>(h16, base + L_W1, b1 + l * PFF, (const float*)0,
                                    (float*)0, ff16, N_TOK, PFF, HID);
        // fused: h = LN2(h + ff @ W2 + b2)  (last layer -> out_h, no fp16 copy)
        tc_gemm_ln<<<N_TOK / 64, 256, GEMM_LN_SMEM>>>(
            ff16, base + L_W2, b2 + l * HID, h32,
            ln2g + l * HID, ln2b + l * HID,
            (l == 1) ? out_h : h32, (l == 1) ? (__half*)0 : h16, PFF);
    }
}

// round 16
// speedup vs baseline: 1.0771x; 1.0771x over previous
#include <cuda_runtime.h>
#include <cuda_fp16.h>
#include <math.h>
#include <stdint.h>

// Problem dims (fixed)
#define BATCH 32
#define SEQ   512
#define N_TOK (BATCH * SEQ)   // 16384
#define DIM   256
#define HID   512
#define PFF   2048
#define NHD   8
#define HDD   64
#define NMAXN 15
#define QKV_STR 1536

// ---------------- scratch (device globals: allocation-free) ----------------
__device__ float  g_x[N_TOK * DIM];
__device__ float  g_tmp[N_TOK * DIM];
__device__ float  g_h32[N_TOK * HID];
__device__ float  g_t1[N_TOK * HID];
__device__ float  g_bqkv[2 * QKV_STR];
__device__ __half g_x16[N_TOK * DIM];
__device__ __half g_agg16[N_TOK * DIM];
__device__ __half g_h16[N_TOK * HID];
__device__ __half g_qkv16[N_TOK * QKV_STR];
__device__ __half g_o16[N_TOK * HID];
__device__ __half g_ff16[N_TOK * PFF];
#define WT_SOC   0
#define WT_PROJ  65536
#define WT_LAYER 196608
#define WT_PER_L 3145728
#define L_QKV 0
#define L_WO  786432
#define L_W1  1048576
#define L_W2  2097152
__device__ __half g_wt16[WT_LAYER + 2 * WT_PER_L];

// ======================= helpers =======================
__device__ __forceinline__ uint32_t smem_u32(const void* p) {
    uint32_t a;
    asm("{ .reg .u64 t; cvta.to.shared.u64 t, %1; cvt.u32.u64 %0, t; }" : "=r"(a) : "l"(p));
    return a;
}
__device__ __forceinline__ void cp16(uint32_t dst, const void* src) {
    asm volatile("cp.async.cg.shared.global [%0], [%1], 16;" :: "r"(dst), "l"(src));
}
#define CP_COMMIT() asm volatile("cp.async.commit_group;" ::: "memory")
#define CP_WAIT(n)  asm volatile("cp.async.wait_group %0;" :: "n"(n) : "memory")

__device__ __forceinline__ void mma_f16(float* c, const uint32_t* a, const uint32_t* b) {
    asm volatile(
        "mma.sync.aligned.m16n8k16.row.col.f32.f16.f16.f32 "
        "{%0,%1,%2,%3}, {%4,%5,%6,%7}, {%8,%9}, {%0,%1,%2,%3};\n"
        : "+f"(c[0]), "+f"(c[1]), "+f"(c[2]), "+f"(c[3])
        : "r"(a[0]), "r"(a[1]), "r"(a[2]), "r"(a[3]), "r"(b[0]), "r"(b[1]));
}
__device__ __forceinline__ void ldsm_x2_t(uint32_t& r0, uint32_t& r1, uint32_t addr) {
    asm volatile("ldmatrix.sync.aligned.m8n8.x2.trans.shared.b16 {%0,%1}, [%2];"
                 : "=r"(r0), "=r"(r1) : "r"(addr));
}
__device__ __forceinline__ uint32_t pack2h(float a, float b) {
    __half2 h = __floats2half2_rn(a, b);
    return *(uint32_t*)&h;
}
__device__ __forceinline__ float warpSum(float v) {
#pragma unroll
    for (int o = 16; o; o >>= 1) v += __shfl_xor_sync(0xffffffffu, v, o);
    return v;
}

// ============== fp16 tensor-core GEMM (Round-8 proven config) ==============
// 128x128 CTA tile, BK=32, 128 threads (4 warps = 2x2), warp tile 64x64, m16n8k16.
// smem rows: 40 halves (80 B); word stride 20 -> banks 4g+tig (CF).
// OUT: 0 = fp32 only, 1 = fp16 only, 2 = both, 3 = fp16 + scale cols<HID by 0.125
#define GSTAGE_B 20480
#define GEMM_SMEM (2 * GSTAGE_B)

template <bool RELU, bool RES, int OUT>
__global__ void __launch_bounds__(128) tc_gemm(const __half* __restrict__ A,
                                               const __half* __restrict__ Bt,
                                               const float* __restrict__ bias,
                                               const float* __restrict__ Cin,
                                               float* __restrict__ C32,
                                               __half* __restrict__ C16,
                                               int M, int N, int K) {
    extern __shared__ char smc[];
    int tid = threadIdx.x;
    int m0 = blockIdx.y * 128, n0 = blockIdx.x * 128;
    int lane = tid & 31, wid = tid >> 5;
    int wm = wid & 1, wn = wid >> 1;
    int g = lane >> 2, tig = lane & 3;
    uint32_t sb = smem_u32(smc);

    float acc[4][8][4];
#pragma unroll
    for (int mt = 0; mt < 4; mt++)
#pragma unroll
        for (int nt = 0; nt < 8; nt++)
#pragma unroll
            for (int r = 0; r < 4; r++) acc[mt][nt][r] = 0.f;

    int nk = K >> 5;

    auto issue = [&](int s, int i) {
#pragma unroll
        for (int p = 0; p < 4; p++) {
            int idx = p * 128 + tid;
            int row = idx >> 2, c = idx & 3;
            uint32_t da = sb + (uint32_t)(s * GSTAGE_B + row * 80 + c * 16);
            uint32_t db = da + 10240;
            cp16(da, A + (size_t)(m0 + row) * K + i * 32 + c * 8);
            cp16(db, Bt + (size_t)(n0 + row) * K + i * 32 + c * 8);
        }
        CP_COMMIT();
    };

    issue(0, 0);
    for (int i = 0; i < nk; i++) {
        int s = i & 1;
        CP_WAIT(0);
        __syncthreads();
        if (i + 1 < nk) issue(s ^ 1, i + 1);
        const uint32_t* As = (const uint32_t*)(smc + s * GSTAGE_B);
        const uint32_t* Bs = As + 2560;
#pragma unroll
        for (int ks = 0; ks < 2; ks++) {
            uint32_t af[4][4], bf[8][2];
#pragma unroll
            for (int mt = 0; mt < 4; mt++) {
                int m = wm * 64 + mt * 16 + g;
                af[mt][0] = As[m * 20 + ks * 8 + tig];
                af[mt][1] = As[(m + 8) * 20 + ks * 8 + tig];
                af[mt][2] = As[m * 20 + ks * 8 + tig + 4];
                af[mt][3] = As[(m + 8) * 20 + ks * 8 + tig + 4];
            }
#pragma unroll
            for (int nt = 0; nt < 8; nt++) {
                int n = wn * 64 + nt * 8 + g;
                bf[nt][0] = Bs[n * 20 + ks * 8 + tig];
                bf[nt][1] = Bs[n * 20 + ks * 8 + tig + 4];
            }
#pragma unroll
            for (int mt = 0; mt < 4; mt++)
#pragma unroll
                for (int nt = 0; nt < 8; nt++)
                    mma_f16(acc[mt][nt], af[mt], bf[nt]);
        }
    }

#pragma unroll
    for (int mt = 0; mt < 4; mt++) {
#pragma unroll
        for (int nt = 0; nt < 8; nt++) {
            int row0 = m0 + wm * 64 + mt * 16 + g;
            int col = n0 + wn * 64 + nt * 8 + tig * 2;
            float b0 = __ldg(&bias[col]), b1 = __ldg(&bias[col + 1]);
            float v0 = acc[mt][nt][0] + b0, v1 = acc[mt][nt][1] + b1;
            float v2 = acc[mt][nt][2] + b0, v3 = acc[mt][nt][3] + b1;
            if (RES) {
                float2 q0 = *(const float2*)(Cin + (size_t)row0 * N + col);
                float2 q1 = *(const float2*)(Cin + (size_t)(row0 + 8) * N + col);
                v0 += q0.x; v1 += q0.y; v2 += q1.x; v3 += q1.y;
            }
            if (RELU) {
                v0 = fmaxf(v0, 0.f); v1 = fmaxf(v1, 0.f);
                v2 = fmaxf(v2, 0.f); v3 = fmaxf(v3, 0.f);
            }
            if (OUT == 3 && col < HID) {
                v0 *= 0.125f; v1 *= 0.125f; v2 *= 0.125f; v3 *= 0.125f;
            }
            if (OUT == 0 || OUT == 2) {
                *(float2*)(C32 + (size_t)row0 * N + col) = make_float2(v0, v1);
                *(float2*)(C32 + (size_t)(row0 + 8) * N + col) = make_float2(v2, v3);
            }
            if (OUT >= 1) {
                *(uint32_t*)(C16 + (size_t)row0 * N + col) = pack2h(v0, v1);
                *(uint32_t*)(C16 + (size_t)(row0 + 8) * N + col) = pack2h(v2, v3);
            }
        }
    }
}

// ============== fp16 flash attention (Round-8 proven: BQ=128, BK=64, dbl-buf KV) =======
#define HOQ  0
#define HOK0 9216
#define HKSZ 4608
#define HOV0 18432
#define HVSZ 4608
#define HOP  27648
#define FOM  18432
#define ATTN_SMEM (73728 + 512)

__global__ void __launch_bounds__(256) attn_mma(const __half* __restrict__ qkv,
                                                const int* __restrict__ src,
                                                __half* __restrict__ O) {
    extern __shared__ char sac[];
    float* saf = (float*)sac;
    const uint32_t* smw = (const uint32_t*)sac;
    uint32_t sb = smem_u32(sac);
    int bh = blockIdx.y;
    int b = bh >> 3, h = bh & 7;
    int q0 = blockIdx.x * 128;
    int tid = threadIdx.x;
    int lane = tid & 31, w = tid >> 5;
    int g = lane >> 2, tig = lane & 3;

    const __half* Qg = qkv + (size_t)(b * SEQ + q0) * QKV_STR + h * HDD;
#pragma unroll
    for (int p = 0; p < 4; p++) {
        int idx = p * 256 + tid;
        int row = idx >> 3, c = idx & 7;
        cp16(sb + (uint32_t)(row * 144 + c * 16), Qg + (size_t)row * QKV_STR + c * 8);
    }
    CP_COMMIT();

    auto load_kv = [&](int s, int kt) {
        const __half* Kg = qkv + (size_t)(b * SEQ + kt * 64) * QKV_STR + HID + h * HDD;
        const __half* Vg = Kg + HID;
#pragma unroll
        for (int p = 0; p < 2; p++) {
            int idx = p * 256 + tid;
            int row = idx >> 3, c = idx & 7;
            cp16(sb + (uint32_t)((HOK0 + s * HKSZ + row * 72) * 2 + c * 16),
                 Kg + (size_t)row * QKV_STR + c * 8);
            cp16(sb + (uint32_t)((HOV0 + s * HVSZ + row * 72) * 2 + c * 16),
                 Vg + (size_t)row * QKV_STR + c * 8);
        }
        CP_COMMIT();
        if (tid < 64)
            saf[FOM + s * 64 + tid] = (src[b * SEQ + kt * 64 + tid] != 0) ? 0.f : -1e10f;
    };

    load_kv(0, 0);

    float o_acc[8][4];
#pragma unroll
    for (int nt = 0; nt < 8; nt++)
#pragma unroll
        for (int r = 0; r < 4; r++) o_acc[nt][r] = 0.f;
    float mr0 = -1e30f, mr1 = -1e30f, lr0 = 0.f, lr1 = 0.f;

    for (int kt = 0; kt < SEQ / 64; kt++) {
        int s = kt & 1;
        CP_WAIT(0);
        __syncthreads();
        if (kt + 1 < SEQ / 64) load_kv(s ^ 1, kt + 1);
        int kbw = (HOK0 + s * HKSZ) >> 1;
        uint32_t vbb = sb + (uint32_t)((HOV0 + s * HVSZ) * 2);
        const float* msk = saf + FOM + s * 64;

        float sc[8][4];
#pragma unroll
        for (int nt = 0; nt < 8; nt++)
#pragma unroll
            for (int r = 0; r < 4; r++) sc[nt][r] = 0.f;
#pragma unroll
        for (int kk = 0; kk < 4; kk++) {
            uint32_t a[4];
            int r0 = (w * 16 + g) * 36 + kk * 8 + tig;
            int r1 = (w * 16 + 8 + g) * 36 + kk * 8 + tig;
            a[0] = smw[r0]; a[1] = smw[r1];
            a[2] = smw[r0 + 4]; a[3] = smw[r1 + 4];
#pragma unroll
            for (int nt = 0; nt < 8; nt++) {
                uint32_t bb[2];
                int rb = kbw + (nt * 8 + g) * 36 + kk * 8 + tig;
                bb[0] = smw[rb]; bb[1] = smw[rb + 4];
                mma_f16(sc[nt], a, bb);
            }
        }

        float m0 = -1e30f, m1 = -1e30f;
#pragma unroll
        for (int nt = 0; nt < 8; nt++) {
            float k0 = msk[nt * 8 + tig * 2];
            float k1 = msk[nt * 8 + tig * 2 + 1];
            sc[nt][0] += k0; sc[nt][1] += k1;
            sc[nt][2] += k0; sc[nt][3] += k1;
            m0 = fmaxf(m0, fmaxf(sc[nt][0], sc[nt][1]));
            m1 = fmaxf(m1, fmaxf(sc[nt][2], sc[nt][3]));
        }
        m0 = fmaxf(m0, __shfl_xor_sync(0xffffffffu, m0, 1));
        m0 = fmaxf(m0, __shfl_xor_sync(0xffffffffu, m0, 2));
        m1 = fmaxf(m1, __shfl_xor_sync(0xffffffffu, m1, 1));
        m1 = fmaxf(m1, __shfl_xor_sync(0xffffffffu, m1, 2));
        float mn0 = fmaxf(mr0, m0), mn1 = fmaxf(mr1, m1);
        float s0 = __expf(mr0 - mn0), s1 = __expf(mr1 - mn1);
        mr0 = mn0; mr1 = mn1;
        float l0 = 0.f, l1 = 0.f;
        uint32_t* smwp = (uint32_t*)sac;
        int pw0 = (HOP >> 1) + (w * 16 + g) * 36 + tig;
        int pw1 = (HOP >> 1) + (w * 16 + 8 + g) * 36 + tig;
#pragma unroll
        for (int nt = 0; nt < 8; nt++) {
            float p0 = __expf(sc[nt][0] - mn0);
            float p1 = __expf(sc[nt][1] - mn0);
            float p2 = __expf(sc[nt][2] - mn1);
            float p3 = __expf(sc[nt][3] - mn1);
            l0 += p0 + p1; l1 += p2 + p3;
            smwp[pw0 + nt * 4] = pack2h(p0, p1);
            smwp[pw1 + nt * 4] = pack2h(p2, p3);
        }
        l0 += __shfl_xor_sync(0xffffffffu, l0, 1);
        l0 += __shfl_xor_sync(0xffffffffu, l0, 2);
        l1 += __shfl_xor_sync(0xffffffffu, l1, 1);
        l1 += __shfl_xor_sync(0xffffffffu, l1, 2);
        lr0 = lr0 * s0 + l0;
        lr1 = lr1 * s1 + l1;
#pragma unroll
        for (int nt = 0; nt < 8; nt++) {
            o_acc[nt][0] *= s0; o_acc[nt][1] *= s0;
            o_acc[nt][2] *= s1; o_acc[nt][3] *= s1;
        }
        __syncwarp();

        int j = lane & 15;
#pragma unroll
        for (int kk = 0; kk < 4; kk++) {
            uint32_t a[4];
            int r0 = (HOP >> 1) + (w * 16 + g) * 36 + kk * 8 + tig;
            int r1 = (HOP >> 1) + (w * 16 + 8 + g) * 36 + kk * 8 + tig;
            a[0] = smwp[r0]; a[1] = smwp[r1];
            a[2] = smwp[r0 + 4]; a[3] = smwp[r1 + 4];
            uint32_t vrow = vbb + (uint32_t)((kk * 16 + j) * 144);
#pragma unroll
            for (int nt = 0; nt < 8; nt++) {
                uint32_t bb0, bb1;
                ldsm_x2_t(bb0, bb1, vrow + nt * 16);
                uint32_t bb[2] = {bb0, bb1};
                mma_f16(o_acc[nt], a, bb);
            }
        }
    }

    float i0 = 1.f / lr0, i1 = 1.f / lr1;
    int row0 = b * SEQ + q0 + w * 16 + g;
    __half* Ob = O + (size_t)row0 * HID + h * HDD;
#pragma unroll
    for (int nt = 0; nt < 8; nt++) {
        *(uint32_t*)(Ob + nt * 8 + tig * 2) = pack2h(o_acc[nt][0] * i0, o_acc[nt][1] * i0);
        *(uint32_t*)(Ob + 8 * HID + nt * 8 + tig * 2) = pack2h(o_acc[nt][2] * i1, o_acc[nt][3] * i1);
    }
}

// ---------------- fused weight transposes (fp32 -> fp16 Bt[n][k]) ----------------
#define NJOBS 14
struct TParams {
    const float* in[NJOBS];
    __half* out[NJOBS];
    int R[NJOBS], C[NJOBS], tstart[NJOBS];
};
__global__ void transpose_all(TParams p) {
    __shared__ float t[32][33];
    int tile = blockIdx.x;
    int j = 0;
#pragma unroll
    for (int q = 1; q < NJOBS; q++)
        if (tile >= p.tstart[q]) j = q;
    int local = tile - p.tstart[j];
    int R = p.R[j], Cc = p.C[j];
    int tilesX = Cc >> 5;
    int c0 = (local % tilesX) * 32, r0 = (local / tilesX) * 32;
    const float* in = p.in[j];
    __half* out = p.out[j];
    int x = threadIdx.x, y = threadIdx.y;
#pragma unroll
    for (int i = 0; i < 32; i += 8) t[y + i][x] = in[(size_t)(r0 + y + i) * Cc + c0 + x];
    __syncthreads();
#pragma unroll
    for (int i = 0; i < 32; i += 8)
        out[(size_t)(c0 + y + i) * R + r0 + x] = __float2half_rn(t[x][y + i]);
}

// ---------------- bias concat (both layers, one launch) ----------------
__global__ void concat_bias(const float* __restrict__ bq, const float* __restrict__ bk,
                            const float* __restrict__ bv, float* __restrict__ out) {
    int i = blockIdx.x * 256 + threadIdx.x;
    int l = i / QKV_STR, r = i % QKV_STR;
    float v;
    if (r < HID) v = bq[l * HID + r];
    else if (r < 2 * HID) v = bk[l * HID + r - HID];
    else v = bv[l * HID + r - 2 * HID];
    out[i] = v;
}

// ---------------- embed + PE + time (vectorized x4, paired sincos) ----------------
// thread handles dims [d4, d4+4); PE pairs (d4,d4+1) share angle, (d4+2,d4+3) share next.
__global__ void __launch_bounds__(256) embed_kernel(const int* __restrict__ src,
                             const float* __restrict__ tint,
                             const float* __restrict__ emb,
                             const float* __restrict__ timeW,
                             const float* __restrict__ timeb,
                             float* __restrict__ x) {
    int t = blockIdx.x * 4 + (threadIdx.x >> 6);
    int d4 = (threadIdx.x & 63) * 4;
    int s = t & (SEQ - 1);
    int v = __ldg(&src[t]);
    float4 e = *(const float4*)(emb + (size_t)v * DIM + d4);
    float4 tw = __ldg((const float4*)(timeW + d4));
    float4 tb = __ldg((const float4*)(timeb + d4));
    float tv = tint[t];
    const float kC = -9.210340371976184f / (float)DIM;
    float div0 = __expf((float)d4 * kC);
    float div1 = __expf((float)(d4 + 2) * kC);
    float sn0, cs0, sn1, cs1;
    __sincosf((float)s * div0, &sn0, &cs0);
    __sincosf((float)s * div1, &sn1, &cs1);
    float4 o;
    o.x = e.x + sn0 + tv * tw.x + tb.x;
    o.y = e.y + cs0 + tv * tw.y + tb.y;
    o.z = e.z + sn1 + tv * tw.z + tb.z;
    o.w = e.w + cs1 + tv * tw.w + tb.w;
    *(float4*)(x + (size_t)t * DIM + d4) = o;
}

// ---------------- neighbor mean aggregation (warp-per-token, float4) --------
__global__ void __launch_bounds__(256) agg_kernel(const int* __restrict__ nidx,
                           const int* __restrict__ ncnt,
                           const float* __restrict__ x,
                           __half* __restrict__ agg) {
    int w = threadIdx.x >> 5, lane = threadIdx.x & 31;
    int n = blockIdx.x * 8 + w;
    int cnt = ncnt[n];
    float4 s0 = make_float4(0.f, 0.f, 0.f, 0.f);
    float4 s1 = s0;
    const int* nb = nidx + n * NMAXN;
    for (int j = 0; j < cnt; j++) {
        int idx = __ldg(&nb[j]);
        const float4* xr = (const float4*)(x + (size_t)idx * DIM);
        float4 a = xr[lane], b = xr[lane + 32];
        s0.x += a.x; s0.y += a.y; s0.z += a.z; s0.w += a.w;
        s1.x += b.x; s1.y += b.y; s1.z += b.z; s1.w += b.w;
    }
    float iv = 1.f / (float)(cnt > 1 ? cnt : 1);
    uint2* ow = (uint2*)(agg + (size_t)n * DIM);
    ow[lane] = make_uint2(pack2h(s0.x * iv, s0.y * iv), pack2h(s0.z * iv, s0.w * iv));
    ow[lane + 32] = make_uint2(pack2h(s1.x * iv, s1.y * iv), pack2h(s1.z * iv, s1.w * iv));
}

// ---------------- soc LN (warp-per-row): writes out_x fp32 + x16 fp16 ----------------
__global__ void __launch_bounds__(256) soc_ln_kernel(const float* __restrict__ tmp,
                              const float* __restrict__ g,
                              const float* __restrict__ beta,
                              const int* __restrict__ ncnt,
                              const int* __restrict__ src,
                              const float* __restrict__ x,
                              __half* __restrict__ x16,
                              float* __restrict__ out_x) {
    int w = threadIdx.x >> 5, lane = threadIdx.x & 31;
    int n = blockIdx.x * 8 + w;
    const float4* r = (const float4*)(tmp + (size_t)n * DIM);
    float4 v[2];
    float s = 0.f;
#pragma unroll
    for (int j = 0; j < 2; j++) {
        v[j] = r[lane + 32 * j];
        s += v[j].x + v[j].y + v[j].z + v[j].w;
    }
    float mu = warpSum(s) * (1.f / DIM);
    float q = 0.f;
#pragma unroll
    for (int j = 0; j < 2; j++) {
        float a = v[j].x - mu, b2 = v[j].y - mu, c = v[j].z - mu, d2 = v[j].w - mu;
        q += a * a + b2 * b2 + c * c + d2 * d2;
    }
    float inv = rsqrtf(warpSum(q) * (1.f / DIM) + 1e-5f);
    int cnt = ncnt[n];
    int pad = (src[n] == 0);
    const float4* gg = (const float4*)g;
    const float4* bb = (const float4*)beta;
    const float4* xr = (const float4*)(x + (size_t)n * DIM);
    float4* ow = (float4*)(out_x + (size_t)n * DIM);
    uint32_t* xw = (uint32_t*)(x16 + (size_t)n * DIM);
#pragma unroll
    for (int j = 0; j < 2; j++) {
        float4 gv = gg[lane + 32 * j], bv = bb[lane + 32 * j];
        float4 xv = xr[lane + 32 * j];
        float y0 = fmaxf((v[j].x - mu) * inv * gv.x + bv.x, 0.f);
        float y1 = fmaxf((v[j].y - mu) * inv * gv.y + bv.y, 0.f);
        float y2 = fmaxf((v[j].z - mu) * inv * gv.z + bv.z, 0.f);
        float y3 = fmaxf((v[j].w - mu) * inv * gv.w + bv.w, 0.f);
        float s0 = (cnt > 0) ? y0 : xv.x; if (pad) s0 = 0.f;
        float s1 = (cnt > 0) ? y1 : xv.y; if (pad) s1 = 0.f;
        float s2 = (cnt > 0) ? y2 : xv.z; if (pad) s2 = 0.f;
        float s3 = (cnt > 0) ? y3 : xv.w; if (pad) s3 = 0.f;
        float o0 = xv.x + 0.2f * s0, o1 = xv.y + 0.2f * s1;
        float o2 = xv.z + 0.2f * s2, o3 = xv.w + 0.2f * s3;
        ow[lane + 32 * j] = make_float4(o0, o1, o2, o3);
        xw[(lane + 32 * j) * 2] = pack2h(o0, o1);
        xw[(lane + 32 * j) * 2 + 1] = pack2h(o2, o3);
    }
}

// ---------------- LayerNorm 512 (warp-per-row): out32 always, out16 optional ----------
__global__ void __launch_bounds__(256) ln512_kernel(const float* __restrict__ in,
                             const float* __restrict__ g,
                             const float* __restrict__ b,
                             float* __restrict__ out32,
                             __half* __restrict__ out16) {
    int w = threadIdx.x >> 5, lane = threadIdx.x & 31;
    int n = blockIdx.x * 8 + w;
    const float4* r = (const float4*)(in + (size_t)n * HID);
    float4 v[4];
    float s = 0.f;
#pragma unroll
    for (int j = 0; j < 4; j++) {
        v[j] = r[lane + 32 * j];
        s += v[j].x + v[j].y + v[j].z + v[j].w;
    }
    float mu = warpSum(s) * (1.f / HID);
    float q = 0.f;
#pragma unroll
    for (int j = 0; j < 4; j++) {
        float a = v[j].x - mu, b2 = v[j].y - mu, c = v[j].z - mu, d2 = v[j].w - mu;
        q += a * a + b2 * b2 + c * c + d2 * d2;
    }
    float inv = rsqrtf(warpSum(q) * (1.f / HID) + 1e-5f);
    const float4* gg = (const float4*)g;
    const float4* bb = (const float4*)b;
    float4* ow = (float4*)(out32 + (size_t)n * HID);
    uint32_t* hw = out16 ? (uint32_t*)(out16 + (size_t)n * HID) : (uint32_t*)0;
#pragma unroll
    for (int j = 0; j < 4; j++) {
        float4 gv = gg[lane + 32 * j], bv = bb[lane + 32 * j];
        float o0 = (v[j].x - mu) * inv * gv.x + bv.x;
        float o1 = (v[j].y - mu) * inv * gv.y + bv.y;
        float o2 = (v[j].z - mu) * inv * gv.z + bv.z;
        float o3 = (v[j].w - mu) * inv * gv.w + bv.w;
        ow[lane + 32 * j] = make_float4(o0, o1, o2, o3);
        if (hw) {
            hw[(lane + 32 * j) * 2] = pack2h(o0, o1);
            hw[(lane + 32 * j) * 2 + 1] = pack2h(o2, o3);
        }
    }
}

// ---------------- host side ----------------
template <bool RELU, bool RES, int OUT>
static void launch_gemm(const __half* A, const __half* Bt, const float* bias,
                        const float* Cin, float* C32, __half* C16, int M, int Nn, int K) {
    dim3 grid(Nn / 128, M / 128);
    tc_gemm<RELU, RES, OUT><<<grid, 128, GEMM_SMEM>>>(A, Bt, bias, Cin, C32, C16, M, Nn, K);
}

extern "C" void kernel_launch(void* const* d_in, const int* in_sizes, int n_in,
                              void* d_out, int out_size) {
    const int*   src   = (const int*)d_in[0];
    const int*   nidx  = (const int*)d_in[2];
    const int*   ncnt  = (const int*)d_in[3];
    const float* tint  = (const float*)d_in[4];
    const float* emb   = (const float*)d_in[5];
    const float* timeW = (const float*)d_in[6];
    const float* timeb = (const float*)d_in[7];
    const float* socW  = (const float*)d_in[8];
    const float* socb  = (const float*)d_in[9];
    const float* socg  = (const float*)d_in[10];
    const float* socbe = (const float*)d_in[11];
    const float* projW = (const float*)d_in[12];
    const float* projb = (const float*)d_in[13];
    const float* Wq    = (const float*)d_in[14];
    const float* bq    = (const float*)d_in[15];
    const float* Wk    = (const float*)d_in[16];
    const float* bk    = (const float*)d_in[17];
    const float* Wv    = (const float*)d_in[18];
    const float* bv    = (const float*)d_in[19];
    const float* Wo    = (const float*)d_in[20];
    const float* bo    = (const float*)d_in[21];
    const float* ln1g  = (const float*)d_in[22];
    const float* ln1b  = (const float*)d_in[23];
    const float* W1    = (const float*)d_in[24];
    const float* b1    = (const float*)d_in[25];
    const float* W2    = (const float*)d_in[26];
    const float* b2    = (const float*)d_in[27];
    const float* ln2g  = (const float*)d_in[28];
    const float* ln2b  = (const float*)d_in[29];

    float *x, *tmp, *h32, *t1, *bqkv;
    __half *x16, *agg16, *h16, *qkv16, *o16, *ff16, *wt16;
    void* p;
    cudaGetSymbolAddress(&p, g_x);     x     = (float*)p;
    cudaGetSymbolAddress(&p, g_tmp);   tmp   = (float*)p;
    cudaGetSymbolAddress(&p, g_h32);   h32   = (float*)p;
    cudaGetSymbolAddress(&p, g_t1);    t1    = (float*)p;
    cudaGetSymbolAddress(&p, g_bqkv);  bqkv  = (float*)p;
    cudaGetSymbolAddress(&p, g_x16);   x16   = (__half*)p;
    cudaGetSymbolAddress(&p, g_agg16); agg16 = (__half*)p;
    cudaGetSymbolAddress(&p, g_h16);   h16   = (__half*)p;
    cudaGetSymbolAddress(&p, g_qkv16); qkv16 = (__half*)p;
    cudaGetSymbolAddress(&p, g_o16);   o16   = (__half*)p;
    cudaGetSymbolAddress(&p, g_ff16);  ff16  = (__half*)p;
    cudaGetSymbolAddress(&p, g_wt16);  wt16  = (__half*)p;

    cudaFuncSetAttribute(tc_gemm<false, true, 0>,  cudaFuncAttributeMaxDynamicSharedMemorySize, GEMM_SMEM);
    cudaFuncSetAttribute(tc_gemm<false, false, 2>, cudaFuncAttributeMaxDynamicSharedMemorySize, GEMM_SMEM);
    cudaFuncSetAttribute(tc_gemm<false, false, 3>, cudaFuncAttributeMaxDynamicSharedMemorySize, GEMM_SMEM);
    cudaFuncSetAttribute(tc_gemm<true, false, 1>,  cudaFuncAttributeMaxDynamicSharedMemorySize, GEMM_SMEM);
    cudaFuncSetAttribute(attn_mma, cudaFuncAttributeMaxDynamicSharedMemorySize, ATTN_SMEM);

    float* out_h = (float*)d_out;
    float* out_x = (float*)d_out + N_TOK * HID;

    // --- fused weight transposes (single launch, fp32 -> fp16) ---
    __half* socT  = wt16 + WT_SOC;
    __half* projT = wt16 + WT_PROJ;
    {
        TParams tp;
        int idx = 0, cum = 0;
        auto add = [&](const float* in, __half* out, int R, int C) {
            tp.in[idx] = in; tp.out[idx] = out; tp.R[idx] = R; tp.C[idx] = C;
            tp.tstart[idx] = cum;
            cum += (R / 32) * (C / 32);
            idx++;
        };
        add(socW, socT, DIM, DIM);
        add(projW, projT, DIM, HID);
        for (int l = 0; l < 2; l++) {
            __half* base = wt16 + WT_LAYER + (size_t)l * WT_PER_L;
            add(Wq + (size_t)l * HID * HID, base + L_QKV + 0 * 262144, HID, HID);
            add(Wk + (size_t)l * HID * HID, base + L_QKV + 1 * 262144, HID, HID);
            add(Wv + (size_t)l * HID * HID, base + L_QKV + 2 * 262144, HID, HID);
            add(Wo + (size_t)l * HID * HID, base + L_WO, HID, HID);
            add(W1 + (size_t)l * HID * PFF, base + L_W1, HID, PFF);
            add(W2 + (size_t)l * PFF * HID, base + L_W2, PFF, HID);
        }
        transpose_all<<<cum, dim3(32, 8)>>>(tp);
    }
    concat_bias<<<12, 256>>>(bq, bk, bv, bqkv);

    // front end
    embed_kernel<<<N_TOK / 4, 256>>>(src, tint, emb, timeW, timeb, x);
    agg_kernel<<<N_TOK / 8, 256>>>(nidx, ncnt, x, agg16);
    launch_gemm<false, true, 0>(agg16, socT, socb, x, tmp, (__half*)0, N_TOK, DIM, DIM);
    soc_ln_kernel<<<N_TOK / 8, 256>>>(tmp, socg, socbe, ncnt, src, x, x16, out_x);
    launch_gemm<false, false, 2>(x16, projT, projb, (const float*)0, h32, h16, N_TOK, HID, DIM);

    for (int l = 0; l < 2; l++) {
        __half* base = wt16 + WT_LAYER + (size_t)l * WT_PER_L;
        launch_gemm<false, false, 3>(h16, base + L_QKV, bqkv + l * QKV_STR, (const float*)0,
                                     (float*)0, qkv16, N_TOK, QKV_STR, HID);
        attn_mma<<<dim3(SEQ / 128, BATCH * NHD), 256, ATTN_SMEM>>>(qkv16, src, o16);
        launch_gemm<false, true, 0>(o16, base + L_WO, bo + l * HID, h32, t1, (__half*)0,
                                    N_TOK, HID, HID);
        ln512_kernel<<<N_TOK / 8, 256>>>(t1, ln1g + l * HID, ln1b + l * HID, h32, h16);
        launch_gemm<true, false, 1>(h16, base + L_W1, b1 + l * PFF, (const float*)0,
                                    (float*)0, ff16, N_TOK, PFF, HID);
        launch_gemm<false, true, 0>(ff16, base + L_W2, b2 + l * HID, h32, t1, (__half*)0,
                                    N_TOK, HID, PFF);
        ln512_kernel<<<N_TOK / 8, 256>>>(t1, ln2g + l * HID, ln2b + l * HID,
                                         (l == 1) ? out_h : h32, (l == 1) ? (__half*)0 : h16);
    }
}